// round 13
// baseline (speedup 1.0000x reference)
#include <cuda_runtime.h>

#define N_NODES 4096
#define D_EMB   256
#define H_HEADS 4
#define DH      64
#define E_EDGES 131072
#define MAXDEG  256
#define ALPHA   0.2f
#define BITW    (N_NODES / 32)

// ---- scratch (__device__ globals; no allocations allowed) ----
// g_bits is zero-initialized at module load; k_scansoft restores zeros after
// reading, so every launch (and every graph replay) sees a cleared bitmask.
__device__ unsigned g_bits[N_NODES * BITW];          // 2 MB dedup bitmask
__device__ int      g_deg [N_NODES];
__device__ int      g_nbr [N_NODES * MAXDEG];        // 4 MB neighbor slots
__device__ float    g_h   [N_NODES * D_EMB];         // 4 MB h[i][head*64+k]
__device__ float    g_esrc[H_HEADS * N_NODES];
__device__ float    g_edst[H_HEADS * N_NODES];
__device__ float    g_wt  [N_NODES * H_HEADS * MAXDEG]; // softmax weights
__device__ float    gw_src[H_HEADS * D_EMB];         // W[h]@a_src[h]
__device__ float    gw_dst[H_HEADS * D_EMB];

__device__ __forceinline__ float leaky(float v) { return v >= 0.f ? v : ALPHA * v; }

// ---- 3xTF32 helpers: a = hi + lo in tf32; hi*hi + hi*lo + lo*hi ~ fp32 ----
__device__ __forceinline__ void totf(float a, unsigned& hi, unsigned& lo) {
    asm("cvt.rna.tf32.f32 %0, %1;" : "=r"(hi) : "f"(a));
    float r = a - __uint_as_float(hi);
    asm("cvt.rna.tf32.f32 %0, %1;" : "=r"(lo) : "f"(r));
}
__device__ __forceinline__ void mma8(float* c, const unsigned* a, const unsigned* b) {
    asm("mma.sync.aligned.m16n8k8.row.col.f32.tf32.tf32.f32 "
        "{%0,%1,%2,%3}, {%4,%5,%6,%7}, {%8,%9}, {%0,%1,%2,%3};"
        : "+f"(c[0]), "+f"(c[1]), "+f"(c[2]), "+f"(c[3])
        : "r"(a[0]), "r"(a[1]), "r"(a[2]), "r"(a[3]), "r"(b[0]), "r"(b[1]));
}

// ---------------------------------------------------------------------------
// 1. RETURN-FREE dedup mark (REDG), 4 edges/thread with vector loads.
//    mask: new_vals>0 <=> edge_vals>0 (edge-MLP sigmoid strictly positive
//    -> the 34-GFLOP MLP is dead code for the output).
// ---------------------------------------------------------------------------
__global__ void k_build(const int* __restrict__ ei, const float* __restrict__ ev) {
    int e = (blockIdx.x * blockDim.x + threadIdx.x) * 4;
    int4   r4 = *(const int4*)&ei[e];
    int4   c4 = *(const int4*)&ei[E_EDGES + e];
    float4 v4 = *(const float4*)&ev[e];
    if (v4.x > 0.f) atomicOr(&g_bits[r4.x * BITW + (c4.x >> 5)], 1u << (c4.x & 31));
    if (v4.y > 0.f) atomicOr(&g_bits[r4.y * BITW + (c4.y >> 5)], 1u << (c4.y & 31));
    if (v4.z > 0.f) atomicOr(&g_bits[r4.z * BITW + (c4.z >> 5)], 1u << (c4.z & 31));
    if (v4.w > 0.f) atomicOr(&g_bits[r4.w * BITW + (c4.w >> 5)], 1u << (c4.w & 31));
}

// ---------------------------------------------------------------------------
// 2. FUSED scan + softmax, warp per row:
//    bitmask -> neighbor list (popc/scan/ffs), re-zero bits, __syncwarp
//    (guarantees memory ordering among participating threads), then the
//    4 heads' softmax weights from the L1-hot list. One launch instead of
//    two + no scan->soft global round trip boundary.
// ---------------------------------------------------------------------------
__global__ void k_scansoft() {
    int r    = blockIdx.x * (blockDim.x >> 5) + (threadIdx.x >> 5);
    int lane = threadIdx.x & 31;
    unsigned w[4];
    int cnt = 0;
    #pragma unroll
    for (int p = 0; p < 4; p++) {
        w[p] = g_bits[r * BITW + lane + 32 * p];
        cnt += __popc(w[p]);
    }
    #pragma unroll
    for (int p = 0; p < 4; p++)                      // restore zeros
        g_bits[r * BITW + lane + 32 * p] = 0u;
    int base = cnt;
    #pragma unroll
    for (int o = 1; o < 32; o <<= 1) {
        int t = __shfl_up_sync(0xffffffffu, base, o);
        if (lane >= o) base += t;
    }
    int total = __shfl_sync(0xffffffffu, base, 31);
    base -= cnt;
    int pos = base;
    #pragma unroll
    for (int p = 0; p < 4; p++) {
        unsigned ww = w[p];
        int cbase = (lane + 32 * p) << 5;
        while (ww) {
            int b = __ffs(ww) - 1;
            ww &= ww - 1;
            if (pos < MAXDEG) g_nbr[r * MAXDEG + pos] = cbase + b;
            pos++;
        }
    }
    int deg = min(total, MAXDEG);
    if (lane == 31) g_deg[r] = deg;
    __syncwarp();                                    // order stores before loads
    if (deg == 0) return;

    const int* nb = &g_nbr[r * MAXDEG];
    if (deg <= 64) {                                 // common path (~99.99%)
        int c0 = nb[lane < deg ? lane : 0];
        int c1 = nb[(32 + lane) < deg ? 32 + lane : 0];
        #pragma unroll
        for (int h = 0; h < H_HEADS; h++) {
            float es = g_esrc[h * N_NODES + r];
            const float* ed = &g_edst[h * N_NODES];
            float* wt = &g_wt[(r * H_HEADS + h) * MAXDEG];
            float e0 = (lane < deg)      ? leaky(es + ed[c0]) : -3.0e38f;
            float e1 = (32 + lane < deg) ? leaky(es + ed[c1]) : -3.0e38f;
            float m = fmaxf(e0, e1);
            #pragma unroll
            for (int o = 16; o; o >>= 1) m = fmaxf(m, __shfl_xor_sync(0xffffffffu, m, o));
            float x0 = (lane < deg)      ? __expf(e0 - m) : 0.f;
            float x1 = (32 + lane < deg) ? __expf(e1 - m) : 0.f;
            float s = x0 + x1;
            #pragma unroll
            for (int o = 16; o; o >>= 1) s += __shfl_xor_sync(0xffffffffu, s, o);
            float inv = 1.0f / s;
            if (lane < deg)      wt[lane]      = x0 * inv;
            if (32 + lane < deg) wt[32 + lane] = x1 * inv;
        }
    } else {
        #pragma unroll
        for (int h = 0; h < H_HEADS; h++) {
            float es = g_esrc[h * N_NODES + r];
            const float* ed = &g_edst[h * N_NODES];
            float* wt = &g_wt[(r * H_HEADS + h) * MAXDEG];
            float m = -3.0e38f;
            for (int j = lane; j < deg; j += 32) m = fmaxf(m, leaky(es + ed[nb[j]]));
            #pragma unroll
            for (int o = 16; o; o >>= 1) m = fmaxf(m, __shfl_xor_sync(0xffffffffu, m, o));
            float s = 0.f;
            for (int j = lane; j < deg; j += 32) s += __expf(leaky(es + ed[nb[j]]) - m);
            #pragma unroll
            for (int o = 16; o; o >>= 1) s += __shfl_xor_sync(0xffffffffu, s, o);
            float inv = 1.0f / s;
            for (int j = lane; j < deg; j += 32)
                wt[j] = __expf(leaky(es + ed[nb[j]]) - m) * inv;
        }
    }
}

// ---------------------------------------------------------------------------
// 3. gw_src[h] = W[h] @ a_src[h] (and dst). Warp per (h,d).
// ---------------------------------------------------------------------------
__global__ void k_vec(const float* __restrict__ W, const float* __restrict__ a_src,
                      const float* __restrict__ a_dst) {
    int wid = blockIdx.x * 8 + (threadIdx.x >> 5);
    int lane = threadIdx.x & 31;
    int h = wid >> 8, d = wid & 255;
    const float* wr = W + (h * D_EMB + d) * DH;
    float w0 = wr[lane], w1 = wr[32 + lane];
    float s = w0 * a_src[h * DH + lane] + w1 * a_src[h * DH + 32 + lane];
    float t = w0 * a_dst[h * DH + lane] + w1 * a_dst[h * DH + 32 + lane];
    #pragma unroll
    for (int o = 16; o; o >>= 1) {
        s += __shfl_xor_sync(0xffffffffu, s, o);
        t += __shfl_xor_sync(0xffffffffu, t, o);
    }
    if (lane == 0) { gw_src[h * D_EMB + d] = s; gw_dst[h * D_EMB + d] = t; }
}

// ---------------------------------------------------------------------------
// 4. esrc/edst GEMV: warp per row, 8 dots per warp.
// ---------------------------------------------------------------------------
__global__ void k_edot(const float* __restrict__ x) {
    __shared__ float2 ws[H_HEADS][128], wd[H_HEADS][128];
    int tid = threadIdx.x;
    for (int l = tid; l < 512; l += 256) {
        ((float2*)ws)[l] = ((const float2*)gw_src)[l];
        ((float2*)wd)[l] = ((const float2*)gw_dst)[l];
    }
    __syncthreads();
    int wi = tid >> 5, lane = tid & 31;
    int i = blockIdx.x * 8 + wi;
    const float2* xr = (const float2*)x + i * 128;
    float2 v[4];
    #pragma unroll
    for (int p = 0; p < 4; p++) v[p] = xr[lane + 32 * p];
    #pragma unroll
    for (int h = 0; h < H_HEADS; h++) {
        float s = 0.f, d = 0.f;
        #pragma unroll
        for (int p = 0; p < 4; p++) {
            float2 a = ws[h][lane + 32 * p];
            float2 b = wd[h][lane + 32 * p];
            s += v[p].x * a.x + v[p].y * a.y;
            d += v[p].x * b.x + v[p].y * b.y;
        }
        #pragma unroll
        for (int o = 16; o; o >>= 1) {
            s += __shfl_xor_sync(0xffffffffu, s, o);
            d += __shfl_xor_sync(0xffffffffu, d, o);
        }
        if (lane == 0) { g_esrc[h * N_NODES + i] = s; g_edst[h * N_NODES + i] = d; }
    }
}

// ---------------------------------------------------------------------------
// 5. h = x @ Wf via 3xTF32 tensor-core MMA (m16n8k8), 128x64 tile per block
//    (blockIdx.y = head), 8 warps, conflict-free padded smem, ~1e-7 accuracy.
// ---------------------------------------------------------------------------
__global__ __launch_bounds__(256) void k_gemm(const float* __restrict__ x,
                                              const float* __restrict__ W) {
    __shared__ float As[128][36];
    __shared__ float Bs[32][72];
    int tid = threadIdx.x, lane = tid & 31, wid = tid >> 5;
    int bm = blockIdx.x * 128;
    int hh = blockIdx.y;
    int m0 = (wid & 3) * 32;
    int n0 = (wid >> 2) * 32;

    float c[2][4][4] = {};

    for (int k0 = 0; k0 < D_EMB; k0 += 32) {
        #pragma unroll
        for (int l = 0; l < 4; l++) {
            int idx = tid + l * 256;
            int r = idx >> 3, c4 = (idx & 7) * 4;
            float4 v = *(const float4*)&x[(bm + r) * D_EMB + k0 + c4];
            As[r][c4] = v.x; As[r][c4 + 1] = v.y; As[r][c4 + 2] = v.z; As[r][c4 + 3] = v.w;
        }
        #pragma unroll
        for (int l = 0; l < 2; l++) {
            int idx = tid + l * 256;
            int kk = idx >> 4, c4 = (idx & 15) * 4;
            float4 v = *(const float4*)&W[hh * (D_EMB * DH) + (k0 + kk) * DH + c4];
            Bs[kk][c4] = v.x; Bs[kk][c4 + 1] = v.y; Bs[kk][c4 + 2] = v.z; Bs[kk][c4 + 3] = v.w;
        }
        __syncthreads();
        #pragma unroll
        for (int kc = 0; kc < 32; kc += 8) {
            unsigned ahi[2][4], alo[2][4];
            #pragma unroll
            for (int ms = 0; ms < 2; ms++) {
                int rb = m0 + ms * 16 + (lane >> 2);
                int kb = kc + (lane & 3);
                totf(As[rb][kb],         ahi[ms][0], alo[ms][0]);
                totf(As[rb + 8][kb],     ahi[ms][1], alo[ms][1]);
                totf(As[rb][kb + 4],     ahi[ms][2], alo[ms][2]);
                totf(As[rb + 8][kb + 4], ahi[ms][3], alo[ms][3]);
            }
            unsigned bhi[4][2], blo[4][2];
            #pragma unroll
            for (int ns = 0; ns < 4; ns++) {
                int nb_ = n0 + ns * 8 + (lane >> 2);
                int kb = kc + (lane & 3);
                totf(Bs[kb][nb_],     bhi[ns][0], blo[ns][0]);
                totf(Bs[kb + 4][nb_], bhi[ns][1], blo[ns][1]);
            }
            #pragma unroll
            for (int ms = 0; ms < 2; ms++)
                #pragma unroll
                for (int ns = 0; ns < 4; ns++) {
                    mma8(c[ms][ns], ahi[ms], bhi[ns]);
                    mma8(c[ms][ns], ahi[ms], blo[ns]);
                    mma8(c[ms][ns], alo[ms], bhi[ns]);
                }
        }
        __syncthreads();
    }
    #pragma unroll
    for (int ms = 0; ms < 2; ms++) {
        int row = bm + m0 + ms * 16 + (lane >> 2);
        #pragma unroll
        for (int ns = 0; ns < 4; ns++) {
            int col = hh * DH + n0 + ns * 8 + 2 * (lane & 3);
            *(float2*)&g_h[row * D_EMB + col]       = make_float2(c[ms][ns][0], c[ms][ns][1]);
            *(float2*)&g_h[(row + 8) * D_EMB + col] = make_float2(c[ms][ns][2], c[ms][ns][3]);
        }
    }
}

// ---------------------------------------------------------------------------
// 6. gather: ONE warp per row, all 4 heads. Lane owns two float4 column
//    slots; 4x unroll -> 8 independent LDG.128 in flight.
// ---------------------------------------------------------------------------
__global__ void k_gat(float* __restrict__ out) {
    int wi = threadIdx.x >> 5, lane = threadIdx.x & 31;
    int i = blockIdx.x * 8 + wi;
    int deg = min(g_deg[i], MAXDEG);
    const int* nb = &g_nbr[i * MAXDEG];
    int ha = lane >> 4;
    const float* wta = &g_wt[(i * H_HEADS + ha)     * MAXDEG];
    const float* wtb = &g_wt[(i * H_HEADS + 2 + ha) * MAXDEG];
    const float4* h4 = (const float4*)g_h;
    int ca = lane;
    int cb = 32 + lane;
    float4 A = make_float4(0.f, 0.f, 0.f, 0.f);
    float4 B = make_float4(0.f, 0.f, 0.f, 0.f);

    int j = 0;
    for (; j + 4 <= deg; j += 4) {
        int c0 = nb[j], c1 = nb[j + 1], c2 = nb[j + 2], c3 = nb[j + 3];
        float wa0 = wta[j], wa1 = wta[j + 1], wa2 = wta[j + 2], wa3 = wta[j + 3];
        float wb0 = wtb[j], wb1 = wtb[j + 1], wb2 = wtb[j + 2], wb3 = wtb[j + 3];
        float4 va0 = h4[c0 * 64 + ca], vb0 = h4[c0 * 64 + cb];
        float4 va1 = h4[c1 * 64 + ca], vb1 = h4[c1 * 64 + cb];
        float4 va2 = h4[c2 * 64 + ca], vb2 = h4[c2 * 64 + cb];
        float4 va3 = h4[c3 * 64 + ca], vb3 = h4[c3 * 64 + cb];
        A.x += wa0 * va0.x + wa1 * va1.x + wa2 * va2.x + wa3 * va3.x;
        A.y += wa0 * va0.y + wa1 * va1.y + wa2 * va2.y + wa3 * va3.y;
        A.z += wa0 * va0.z + wa1 * va1.z + wa2 * va2.z + wa3 * va3.z;
        A.w += wa0 * va0.w + wa1 * va1.w + wa2 * va2.w + wa3 * va3.w;
        B.x += wb0 * vb0.x + wb1 * vb1.x + wb2 * vb2.x + wb3 * vb3.x;
        B.y += wb0 * vb0.y + wb1 * vb1.y + wb2 * vb2.y + wb3 * vb3.y;
        B.z += wb0 * vb0.z + wb1 * vb1.z + wb2 * vb2.z + wb3 * vb3.z;
        B.w += wb0 * vb0.w + wb1 * vb1.w + wb2 * vb2.w + wb3 * vb3.w;
    }
    for (; j < deg; j++) {
        int c0 = nb[j];
        float wa = wta[j], wb = wtb[j];
        float4 va = h4[c0 * 64 + ca], vb = h4[c0 * 64 + cb];
        A.x += wa * va.x; A.y += wa * va.y; A.z += wa * va.z; A.w += wa * va.w;
        B.x += wb * vb.x; B.y += wb * vb.y; B.z += wb * vb.z; B.w += wb * vb.w;
    }
    if (deg == 0) {   // reference degenerates to uniform 1/N mean; P ~ e^-32
        float4 sa = make_float4(0.f, 0.f, 0.f, 0.f);
        float4 sb = make_float4(0.f, 0.f, 0.f, 0.f);
        for (int r = 0; r < N_NODES; r++) {
            float4 va = h4[r * 64 + ca], vb = h4[r * 64 + cb];
            sa.x += va.x; sa.y += va.y; sa.z += va.z; sa.w += va.w;
            sb.x += vb.x; sb.y += vb.y; sb.z += vb.z; sb.w += vb.w;
        }
        const float inv = 1.0f / N_NODES;
        A = make_float4(sa.x * inv, sa.y * inv, sa.z * inv, sa.w * inv);
        B = make_float4(sb.x * inv, sb.y * inv, sb.z * inv, sb.w * inv);
    }
    float4* o4 = (float4*)out;
    o4[i * 64 + ca] = A;
    o4[i * 64 + cb] = B;
}

// ---------------------------------------------------------------------------
// inputs: 0 x 1 edge_vals 2 W1 3 b1 4 W2 5 b2 (2..5 dead code) 6 W 7 a_src
// 8 a_dst 9 edge_index.
// DAG: main: build -> [edot] -> scansoft -> [gemm] -> gat
//      s2:   gemm (tensor cores)        s3: vec -> edot
// ---------------------------------------------------------------------------
extern "C" void kernel_launch(void* const* d_in, const int* in_sizes, int n_in,
                              void* d_out, int out_size) {
    const float* x     = (const float*)d_in[0];
    const float* ev    = (const float*)d_in[1];
    const float* W     = (const float*)d_in[6];
    const float* a_src = (const float*)d_in[7];
    const float* a_dst = (const float*)d_in[8];
    const int*   ei    = (const int*)d_in[9];
    float* out = (float*)d_out;

    static cudaStream_t s2 = nullptr, s3 = nullptr;
    static cudaEvent_t  e_fork = nullptr, e_gemm = nullptr, e_edot = nullptr;
    if (!s2) {
        cudaStreamCreateWithFlags(&s2, cudaStreamNonBlocking);
        cudaStreamCreateWithFlags(&s3, cudaStreamNonBlocking);
        cudaEventCreateWithFlags(&e_fork, cudaEventDisableTiming);
        cudaEventCreateWithFlags(&e_gemm, cudaEventDisableTiming);
        cudaEventCreateWithFlags(&e_edot, cudaEventDisableTiming);
    }

    cudaEventRecord(e_fork, 0);
    cudaStreamWaitEvent(s2, e_fork, 0);
    cudaStreamWaitEvent(s3, e_fork, 0);

    k_gemm<<<dim3(N_NODES / 128, H_HEADS), 256, 0, s2>>>(x, W);
    cudaEventRecord(e_gemm, s2);

    k_vec<<<128, 256, 0, s3>>>(W, a_src, a_dst);
    k_edot<<<N_NODES / 8, 256, 0, s3>>>(x);
    cudaEventRecord(e_edot, s3);

    k_build<<<E_EDGES / 1024, 256>>>(ei, ev);
    cudaStreamWaitEvent(0, e_edot, 0);
    k_scansoft<<<N_NODES / 8, 256>>>();

    cudaStreamWaitEvent(0, e_gemm, 0);
    k_gat<<<N_NODES / 8, 256>>>(out);
}